// round 3
// baseline (speedup 1.0000x reference)
#include <cuda_runtime.h>
#include <cuda_bf16.h>
#include <cstdint>

// Problem constants
#define Bv   16
#define Sv   2048
#define Ev   256
#define Hv   4
#define Lv   2
#define NQv  8
#define FFNv 512
#define Cv   2
#define TOKENS (Bv * Sv)          // 32768
#define TB   32                   // tokens per block in the fused layer kernels
#define CSTRIDE 36                // padded [e][t] stride (floats): 16B-aligned rows, 4-way max write conflict

// Scratch activations [TOKENS][E] — device global (no allocation allowed)
__device__ float g_x[(size_t)TOKENS * Ev];

// ---------------- packed f32x2 helpers ----------------
__device__ __forceinline__ unsigned long long pack2(float lo, float hi) {
    unsigned long long r;
    asm("mov.b64 %0, {%1, %2};" : "=l"(r) : "f"(lo), "f"(hi));
    return r;
}
__device__ __forceinline__ void unpack2(unsigned long long v, float& lo, float& hi) {
    asm("mov.b64 {%0, %1}, %2;" : "=f"(lo), "=f"(hi) : "l"(v));
}
__device__ __forceinline__ unsigned long long ffma2(unsigned long long a,
                                                    unsigned long long b,
                                                    unsigned long long c) {
    unsigned long long d;
    asm("fma.rn.f32x2 %0, %1, %2, %3;" : "=l"(d) : "l"(a), "l"(b), "l"(c));
    return d;
}

// ---------------- kernel 1: embedding + sinusoidal positional encoding ----------------
__global__ __launch_bounds__(256) void embed_pe_kernel(
    const int* __restrict__ tokens, const float* __restrict__ embed)
{
    int tok = blockIdx.x;
    int e = threadIdx.x;
    int s = tok & (Sv - 1);
    int id = tokens[tok];
    float v = embed[(size_t)id * Ev + e];
    // div = exp(2i * (-ln(10000)/E)); even e -> sin, odd e -> cos, i = e/2 (2i = e&~1)
    float di = (float)(e & ~1);
    float dv = expf(di * (-9.210340371976184f / (float)Ev));
    float arg = (float)s * dv;
    float pe = (e & 1) ? cosf(arg) : sinf(arg);
    g_x[(size_t)tok * Ev + e] = v + pe;
}

// ---------------- warp-level layernorm over E=256, TB tokens, 8 warps ----------------
// rr: smem [t*256 + f] residual values; writes mean/var into mbuf/vbuf
__device__ __forceinline__ void block_ln_stats(
    const float* __restrict__ rr, float* __restrict__ mbuf, float* __restrict__ vbuf,
    int f)
{
    int wid = f >> 5, lane = f & 31;
    #pragma unroll
    for (int k = 0; k < TB / 8; k++) {
        int t = wid * (TB / 8) + k;
        float s = 0.f, ss = 0.f;
        #pragma unroll
        for (int j = 0; j < 8; j++) {
            float v = rr[t * Ev + lane + 32 * j];
            s += v; ss += v * v;
        }
        #pragma unroll
        for (int o = 16; o > 0; o >>= 1) {
            s  += __shfl_xor_sync(0xffffffffu, s, o);
            ss += __shfl_xor_sync(0xffffffffu, ss, o);
        }
        if (lane == 0) {
            float m = s * (1.0f / Ev);
            mbuf[t] = m;
            vbuf[t] = ss * (1.0f / Ev) - m * m;
        }
    }
}

// ---------------- kernel 2: attn = cos(x+theta)@W + b; x = LN(x + attn) ----------------
__global__ __launch_bounds__(256) void attn_ln_kernel(
    const float* __restrict__ theta,   // [64] (tiled over heads -> index e%64)
    const float* __restrict__ Wc,      // [E][E], row e contiguous in f
    const float* __restrict__ bc,      // [E]
    const float* __restrict__ g1, const float* __restrict__ b1)
{
    __shared__ __align__(16) float c2[Ev * CSTRIDE];   // cos vals, layout [e][t], 36KB
    __shared__ float mbuf[TB], vbuf[TB];

    int f = threadIdx.x;
    size_t base = (size_t)blockIdx.x * TB * Ev;
    float th = theta[f & 63];

    #pragma unroll 8
    for (int t = 0; t < TB; t++)
        c2[f * CSTRIDE + t] = cosf(g_x[base + (size_t)t * Ev + f] + th);
    __syncthreads();

    unsigned long long acc[TB / 2];
    #pragma unroll
    for (int p = 0; p < TB / 2; p++) acc[p] = 0ull;

    for (int e = 0; e < Ev; e++) {
        float w = Wc[e * Ev + f];
        unsigned long long wp = pack2(w, w);
        const ulonglong2* row = reinterpret_cast<const ulonglong2*>(c2 + e * CSTRIDE);
        #pragma unroll
        for (int p = 0; p < TB / 4; p++) {
            ulonglong2 cc = row[p];
            acc[2 * p]     = ffma2(cc.x, wp, acc[2 * p]);
            acc[2 * p + 1] = ffma2(cc.y, wp, acc[2 * p + 1]);
        }
    }

    float bias = bc[f];
    float r[TB];
    #pragma unroll
    for (int p = 0; p < TB / 2; p++) {
        float lo, hi;
        unpack2(acc[p], lo, hi);
        r[2 * p]     = g_x[base + (size_t)(2 * p) * Ev + f]     + lo + bias;
        r[2 * p + 1] = g_x[base + (size_t)(2 * p + 1) * Ev + f] + hi + bias;
    }
    __syncthreads();                  // all done reading c2

    float* rr = c2;                   // reuse: 32*256 = 8192 floats <= 9216
    #pragma unroll 8
    for (int t = 0; t < TB; t++) rr[t * Ev + f] = r[t];
    __syncthreads();

    block_ln_stats(rr, mbuf, vbuf, f);
    __syncthreads();

    float gg = g1[f], bb = b1[f];
    #pragma unroll 8
    for (int t = 0; t < TB; t++) {
        float inv = rsqrtf(vbuf[t] + 1e-5f);
        g_x[base + (size_t)t * Ev + f] = (r[t] - mbuf[t]) * inv * gg + bb;
    }
}

// ---------------- kernel 3: q=cos(x[:8])*cos(th); h=relu(q@W1+b1); ffn=h@W2+b2; x=LN(x+ffn) ----------------
__global__ __launch_bounds__(256) void ffn_ln_kernel(
    const float* __restrict__ fth,     // [8]
    const float* __restrict__ W1,      // [8][512]
    const float* __restrict__ b1v,     // [512]
    const float* __restrict__ W2,      // [512][256]
    const float* __restrict__ b2v,     // [256]
    const float* __restrict__ g2, const float* __restrict__ b2g)
{
    __shared__ __align__(16) float h2[256 * CSTRIDE]; // one 256-wide FFN chunk, [j][t], 36KB
    __shared__ float q[TB][NQv];
    __shared__ float mbuf[TB], vbuf[TB];

    int f = threadIdx.x;
    size_t base = (size_t)blockIdx.x * TB * Ev;

    {   // 256 threads cover 32 tokens x 8 qubits
        int t = f >> 3, n = f & 7;
        q[t][n] = cosf(g_x[base + (size_t)t * Ev + n]) * cosf(fth[n]);
    }

    unsigned long long acc[TB / 2];
    #pragma unroll
    for (int p = 0; p < TB / 2; p++) acc[p] = 0ull;

    for (int jc = 0; jc < FFNv / 256; jc++) {
        __syncthreads();              // q ready (iter 0) / previous chunk fully consumed
        int j = jc * 256 + f;
        float w1r[NQv];
        #pragma unroll
        for (int n = 0; n < NQv; n++) w1r[n] = W1[n * FFNv + j];
        float bb = b1v[j];
        #pragma unroll 4
        for (int t = 0; t < TB; t++) {
            float s = bb;
            #pragma unroll
            for (int n = 0; n < NQv; n++) s += q[t][n] * w1r[n];
            h2[f * CSTRIDE + t] = fmaxf(s, 0.f);
        }
        __syncthreads();

        for (int jj = 0; jj < 256; jj++) {
            float w = W2[(jc * 256 + jj) * Ev + f];
            unsigned long long wp = pack2(w, w);
            const ulonglong2* row = reinterpret_cast<const ulonglong2*>(h2 + jj * CSTRIDE);
            #pragma unroll
            for (int p = 0; p < TB / 4; p++) {
                ulonglong2 cc = row[p];
                acc[2 * p]     = ffma2(cc.x, wp, acc[2 * p]);
                acc[2 * p + 1] = ffma2(cc.y, wp, acc[2 * p + 1]);
            }
        }
    }

    float bias = b2v[f];
    float r[TB];
    #pragma unroll
    for (int p = 0; p < TB / 2; p++) {
        float lo, hi;
        unpack2(acc[p], lo, hi);
        r[2 * p]     = g_x[base + (size_t)(2 * p) * Ev + f]     + lo + bias;
        r[2 * p + 1] = g_x[base + (size_t)(2 * p + 1) * Ev + f] + hi + bias;
    }
    __syncthreads();

    float* rr = h2;                   // reuse (8192 <= 9216 floats)
    #pragma unroll 8
    for (int t = 0; t < TB; t++) rr[t * Ev + f] = r[t];
    __syncthreads();

    block_ln_stats(rr, mbuf, vbuf, f);
    __syncthreads();

    float gg = g2[f], bb = b2g[f];
    #pragma unroll 8
    for (int t = 0; t < TB; t++) {
        float inv = rsqrtf(vbuf[t] + 1e-5f);
        g_x[base + (size_t)t * Ev + f] = (r[t] - mbuf[t]) * inv * gg + bb;
    }
}

// ---------------- kernel 4: pooled = mean_s(x); out = pooled @ cls_w + cls_b ----------------
__global__ __launch_bounds__(256) void pool_cls_kernel(
    const float* __restrict__ cw,     // [E][2]
    const float* __restrict__ cb,     // [2]
    float* __restrict__ out)          // [B][2]
{
    int b = blockIdx.x;
    int tid = threadIdx.x;
    int e4 = (tid & 63) << 2;         // float4 column group
    int grp = tid >> 6;               // 4 s-strided groups

    const float4* xp = reinterpret_cast<const float4*>(g_x + (size_t)b * Sv * Ev);
    float4 a = make_float4(0.f, 0.f, 0.f, 0.f);
    for (int s = grp; s < Sv; s += 4) {
        float4 v = xp[(size_t)s * (Ev / 4) + (e4 >> 2)];
        a.x += v.x; a.y += v.y; a.z += v.z; a.w += v.w;
    }

    __shared__ float part[4 * Ev];
    part[grp * Ev + e4 + 0] = a.x;
    part[grp * Ev + e4 + 1] = a.y;
    part[grp * Ev + e4 + 2] = a.z;
    part[grp * Ev + e4 + 3] = a.w;
    __syncthreads();

    __shared__ float red0[256], red1[256];
    float pooled = (part[tid] + part[Ev + tid] + part[2 * Ev + tid] + part[3 * Ev + tid])
                   * (1.0f / Sv);
    red0[tid] = pooled * cw[tid * Cv + 0];
    red1[tid] = pooled * cw[tid * Cv + 1];
    __syncthreads();
    #pragma unroll
    for (int o = 128; o > 0; o >>= 1) {
        if (tid < o) { red0[tid] += red0[tid + o]; red1[tid] += red1[tid + o]; }
        __syncthreads();
    }
    if (tid == 0) {
        out[b * Cv + 0] = red0[0] + cb[0];
        out[b * Cv + 1] = red1[0] + cb[1];
    }
}

// ---------------- launch ----------------
extern "C" void kernel_launch(void* const* d_in, const int* in_sizes, int n_in,
                              void* d_out, int out_size)
{
    const int*   tokens     = (const int*)  d_in[0];
    const float* embed      = (const float*)d_in[1];
    const float* attn_theta = (const float*)d_in[2];   // [L,64]
    const float* combine_w  = (const float*)d_in[3];   // [L,E,E]
    const float* combine_b  = (const float*)d_in[4];   // [L,E]
    const float* ffn_theta  = (const float*)d_in[5];   // [L,8]
    const float* lin1_w     = (const float*)d_in[6];   // [L,8,512]
    const float* lin1_b     = (const float*)d_in[7];   // [L,512]
    const float* lin2_w     = (const float*)d_in[8];   // [L,512,256]
    const float* lin2_b     = (const float*)d_in[9];   // [L,256]
    const float* ln1_g      = (const float*)d_in[10];  // [L,E]
    const float* ln1_b      = (const float*)d_in[11];
    const float* ln2_g      = (const float*)d_in[12];
    const float* ln2_b      = (const float*)d_in[13];
    const float* cls_w      = (const float*)d_in[14];  // [E,2]
    const float* cls_b      = (const float*)d_in[15];  // [2]
    float* out = (float*)d_out;

    embed_pe_kernel<<<TOKENS, 256>>>(tokens, embed);

    for (int l = 0; l < Lv; l++) {
        attn_ln_kernel<<<TOKENS / TB, 256>>>(
            attn_theta + l * (Ev / Hv),
            combine_w  + (size_t)l * Ev * Ev,
            combine_b  + l * Ev,
            ln1_g + l * Ev, ln1_b + l * Ev);

        ffn_ln_kernel<<<TOKENS / TB, 256>>>(
            ffn_theta + l * NQv,
            lin1_w + (size_t)l * NQv * FFNv,
            lin1_b + l * FFNv,
            lin2_w + (size_t)l * FFNv * Ev,
            lin2_b + l * Ev,
            ln2_g + l * Ev, ln2_b + l * Ev);
    }

    pool_cls_kernel<<<Bv, 256>>>(cls_w, cls_b, out);
}

// round 5
// speedup vs baseline: 2.2326x; 2.2326x over previous
#include <cuda_runtime.h>
#include <cuda_bf16.h>
#include <cstdint>

// Problem constants
#define Bv   16
#define Sv   2048
#define Ev   256
#define Hv   4
#define Lv   2
#define NQv  8
#define FFNv 512
#define Cv   2
#define TOKENS (Bv * Sv)          // 32768
#define TB   32                   // tokens per block in fused layer kernels

// Scratch activations [TOKENS][E] — device global (no allocation allowed)
__device__ float g_x[(size_t)TOKENS * Ev];
// pool partials [B][8][E]
__device__ float g_part[Bv * 8 * Ev];

typedef unsigned long long ull;

// ---------------- packed f32x2 helpers ----------------
__device__ __forceinline__ ull pack2(float lo, float hi) {
    ull r;
    asm("mov.b64 %0, {%1, %2};" : "=l"(r) : "f"(lo), "f"(hi));
    return r;
}
__device__ __forceinline__ void unpack2(ull v, float& lo, float& hi) {
    asm("mov.b64 {%0, %1}, %2;" : "=f"(lo), "=f"(hi) : "l"(v));
}
__device__ __forceinline__ ull ffma2(ull a, ull b, ull c) {
    ull d;
    asm("fma.rn.f32x2 %0, %1, %2, %3;" : "=l"(d) : "l"(a), "l"(b), "l"(c));
    return d;
}

// ---------------- kernel 1: embedding + sinusoidal positional encoding ----------------
__global__ __launch_bounds__(256) void embed_pe_kernel(
    const int* __restrict__ tokens, const float* __restrict__ embed)
{
    int e = threadIdx.x;
    float dv = expf((float)(e & ~1) * (-9.210340371976184f / (float)Ev));
    bool odd = (e & 1);
    int tok0 = blockIdx.x * 8;
    #pragma unroll
    for (int k = 0; k < 8; k++) {
        int tok = tok0 + k;
        int s = tok & (Sv - 1);
        int id = tokens[tok];
        float arg = (float)s * dv;
        float pe = odd ? cosf(arg) : sinf(arg);
        g_x[(size_t)tok * Ev + e] = embed[(size_t)id * Ev + e] + pe;
    }
}

// ---------------- shared GEMM inner step: 8 tokens x 8 f per thread ----------------
// A,Bt: packed token-pairs (t0..t0+3 / t0+4..t0+7); w0,w1: 8 weight scalars.
#define GEMM_STEP(A, Bt, w0, w1, acc)                                    \
    do {                                                                 \
        ull wp;                                                          \
        wp = pack2((w0).x, (w0).x);                                      \
        acc[0][0]=ffma2((A).x,wp,acc[0][0]); acc[1][0]=ffma2((A).y,wp,acc[1][0]); \
        acc[2][0]=ffma2((Bt).x,wp,acc[2][0]); acc[3][0]=ffma2((Bt).y,wp,acc[3][0]); \
        wp = pack2((w0).y, (w0).y);                                      \
        acc[0][1]=ffma2((A).x,wp,acc[0][1]); acc[1][1]=ffma2((A).y,wp,acc[1][1]); \
        acc[2][1]=ffma2((Bt).x,wp,acc[2][1]); acc[3][1]=ffma2((Bt).y,wp,acc[3][1]); \
        wp = pack2((w0).z, (w0).z);                                      \
        acc[0][2]=ffma2((A).x,wp,acc[0][2]); acc[1][2]=ffma2((A).y,wp,acc[1][2]); \
        acc[2][2]=ffma2((Bt).x,wp,acc[2][2]); acc[3][2]=ffma2((Bt).y,wp,acc[3][2]); \
        wp = pack2((w0).w, (w0).w);                                      \
        acc[0][3]=ffma2((A).x,wp,acc[0][3]); acc[1][3]=ffma2((A).y,wp,acc[1][3]); \
        acc[2][3]=ffma2((Bt).x,wp,acc[2][3]); acc[3][3]=ffma2((Bt).y,wp,acc[3][3]); \
        wp = pack2((w1).x, (w1).x);                                      \
        acc[0][4]=ffma2((A).x,wp,acc[0][4]); acc[1][4]=ffma2((A).y,wp,acc[1][4]); \
        acc[2][4]=ffma2((Bt).x,wp,acc[2][4]); acc[3][4]=ffma2((Bt).y,wp,acc[3][4]); \
        wp = pack2((w1).y, (w1).y);                                      \
        acc[0][5]=ffma2((A).x,wp,acc[0][5]); acc[1][5]=ffma2((A).y,wp,acc[1][5]); \
        acc[2][5]=ffma2((Bt).x,wp,acc[2][5]); acc[3][5]=ffma2((Bt).y,wp,acc[3][5]); \
        wp = pack2((w1).z, (w1).z);                                      \
        acc[0][6]=ffma2((A).x,wp,acc[0][6]); acc[1][6]=ffma2((A).y,wp,acc[1][6]); \
        acc[2][6]=ffma2((Bt).x,wp,acc[2][6]); acc[3][6]=ffma2((Bt).y,wp,acc[3][6]); \
        wp = pack2((w1).w, (w1).w);                                      \
        acc[0][7]=ffma2((A).x,wp,acc[0][7]); acc[1][7]=ffma2((A).y,wp,acc[1][7]); \
        acc[2][7]=ffma2((Bt).x,wp,acc[2][7]); acc[3][7]=ffma2((Bt).y,wp,acc[3][7]); \
    } while (0)

// Epilogue+LN shared by both layer kernels.
// rr: smem [32][256]; acc holds thread tile; xres = residual source (g_x+base).
__device__ __forceinline__ void epilogue_ln(
    ull acc[4][8], float* rr, const float* xres,
    const float* __restrict__ bias, const float* __restrict__ lng,
    const float* __restrict__ lnb, float* mbuf, float* vbuf,
    int tid, int lane, int t0, float* xout)
{
    const float4 bc0 = *(const float4*)(bias + 4 * lane);
    const float4 bc1 = *(const float4*)(bias + 128 + 4 * lane);
    #pragma unroll
    for (int tp = 0; tp < 4; tp++) {
        int ta = t0 + 2 * tp;
        const float* xa = xres + (size_t)ta * Ev;
        float4 xa0 = *(const float4*)(xa + 4 * lane);
        float4 xa1 = *(const float4*)(xa + 128 + 4 * lane);
        float4 xb0 = *(const float4*)(xa + Ev + 4 * lane);
        float4 xb1 = *(const float4*)(xa + Ev + 128 + 4 * lane);
        float l0,h0,l1,h1,l2,h2,l3,h3;
        unpack2(acc[tp][0], l0, h0);
        unpack2(acc[tp][1], l1, h1);
        unpack2(acc[tp][2], l2, h2);
        unpack2(acc[tp][3], l3, h3);
        float4 ra0 = make_float4(xa0.x+l0+bc0.x, xa0.y+l1+bc0.y, xa0.z+l2+bc0.z, xa0.w+l3+bc0.w);
        float4 rb0 = make_float4(xb0.x+h0+bc0.x, xb0.y+h1+bc0.y, xb0.z+h2+bc0.z, xb0.w+h3+bc0.w);
        unpack2(acc[tp][4], l0, h0);
        unpack2(acc[tp][5], l1, h1);
        unpack2(acc[tp][6], l2, h2);
        unpack2(acc[tp][7], l3, h3);
        float4 ra1 = make_float4(xa1.x+l0+bc1.x, xa1.y+l1+bc1.y, xa1.z+l2+bc1.z, xa1.w+l3+bc1.w);
        float4 rb1 = make_float4(xb1.x+h0+bc1.x, xb1.y+h1+bc1.y, xb1.z+h2+bc1.z, xb1.w+h3+bc1.w);
        *(float4*)(rr + ta * Ev + 4 * lane)            = ra0;
        *(float4*)(rr + ta * Ev + 128 + 4 * lane)      = ra1;
        *(float4*)(rr + (ta + 1) * Ev + 4 * lane)      = rb0;
        *(float4*)(rr + (ta + 1) * Ev + 128 + 4 * lane)= rb1;
    }
    __syncthreads();

    // LN stats: warp handles tokens t0..t0+7
    #pragma unroll
    for (int k = 0; k < 8; k++) {
        int t = t0 + k;
        float s = 0.f, ss = 0.f;
        #pragma unroll
        for (int j = 0; j < 8; j++) {
            float v = rr[t * Ev + lane + 32 * j];
            s += v; ss += v * v;
        }
        #pragma unroll
        for (int o = 16; o > 0; o >>= 1) {
            s  += __shfl_xor_sync(0xffffffffu, s, o);
            ss += __shfl_xor_sync(0xffffffffu, ss, o);
        }
        if (lane == 0) {
            float m = s * (1.0f / Ev);
            mbuf[t] = m;
            vbuf[t] = rsqrtf(ss * (1.0f / Ev) - m * m + 1e-5f);
        }
    }
    __syncthreads();

    float gg0 = lng[tid],       bb0 = lnb[tid];
    float gg1 = lng[tid + 128], bb1 = lnb[tid + 128];
    #pragma unroll 4
    for (int t = 0; t < TB; t++) {
        float m = mbuf[t], inv = vbuf[t];
        float* xo = xout + (size_t)t * Ev;
        xo[tid]       = (rr[t * Ev + tid]       - m) * inv * gg0 + bb0;
        xo[tid + 128] = (rr[t * Ev + tid + 128] - m) * inv * gg1 + bb1;
    }
}

// ---------------- kernel 2: attn = cos(x+theta)@W + b; x = LN(x + attn) ----------------
__global__ __launch_bounds__(128, 4) void attn_ln_kernel(
    const float* __restrict__ theta,   // [64]
    const float* __restrict__ Wc,      // [E][E]
    const float* __restrict__ bc,      // [E]
    const float* __restrict__ g1, const float* __restrict__ b1)
{
    __shared__ __align__(16) float a[Ev * TB];  // [e][t] cos acts / later rr[32][256]
    __shared__ float sth[64];
    __shared__ float mbuf[TB], vbuf[TB];

    int tid = threadIdx.x, lane = tid & 31, w = tid >> 5;
    size_t base = (size_t)blockIdx.x * TB * Ev;
    int t0 = w * 8;

    if (tid < 64) sth[tid] = theta[tid];
    __syncthreads();

    // Phase A: cos(x + theta), transpose to [e][t]
    {
        const float* xp = g_x + base + (size_t)lane * Ev + w * 64;
        int erow = w * 64;
        #pragma unroll
        for (int i = 0; i < 64; i += 4) {
            float4 v = *(const float4*)(xp + i);
            a[(erow + i + 0) * TB + lane] = cosf(v.x + sth[i + 0]);
            a[(erow + i + 1) * TB + lane] = cosf(v.y + sth[i + 1]);
            a[(erow + i + 2) * TB + lane] = cosf(v.z + sth[i + 2]);
            a[(erow + i + 3) * TB + lane] = cosf(v.w + sth[i + 3]);
        }
    }
    __syncthreads();

    ull acc[4][8];
    #pragma unroll
    for (int p = 0; p < 4; p++)
        #pragma unroll
        for (int q = 0; q < 8; q++) acc[p][q] = 0ull;

    const float* Wp = Wc + 4 * lane;
    #pragma unroll 2
    for (int e = 0; e < Ev; e++) {
        ulonglong2 A  = *(const ulonglong2*)(a + e * TB + t0);
        ulonglong2 Bt = *(const ulonglong2*)(a + e * TB + t0 + 4);
        float4 w0 = *(const float4*)(Wp + e * Ev);
        float4 w1 = *(const float4*)(Wp + e * Ev + 128);
        GEMM_STEP(A, Bt, w0, w1, acc);
    }
    __syncthreads();   // done reading a; reuse as rr

    epilogue_ln(acc, a, g_x + base, bc, g1, b1, mbuf, vbuf,
                tid, lane, t0, g_x + base);
}

// ---------------- kernel 3: FFN + LN ----------------
__global__ __launch_bounds__(128, 4) void ffn_ln_kernel(
    const float* __restrict__ fth,     // [8]
    const float* __restrict__ W1,      // [8][512]
    const float* __restrict__ b1v,     // [512]
    const float* __restrict__ W2,      // [512][256]
    const float* __restrict__ b2v,     // [256]
    const float* __restrict__ g2, const float* __restrict__ b2g)
{
    __shared__ __align__(16) float hbuf[256 * TB]; // chunk [j][t] / later rr[32][256]
    __shared__ float q[TB][NQv];
    __shared__ float mbuf[TB], vbuf[TB];

    int tid = threadIdx.x, lane = tid & 31, w = tid >> 5;
    size_t base = (size_t)blockIdx.x * TB * Ev;
    int t0 = w * 8;

    for (int i = tid; i < TB * NQv; i += 128) {
        int t = i >> 3, n = i & 7;
        q[t][n] = cosf(g_x[base + (size_t)t * Ev + n]) * cosf(fth[n]);
    }

    ull acc[4][8];
    #pragma unroll
    for (int p = 0; p < 4; p++)
        #pragma unroll
        for (int qq = 0; qq < 8; qq++) acc[p][qq] = 0ull;

    for (int jc = 0; jc < FFNv / 256; jc++) {
        __syncthreads();   // q ready / previous chunk consumed

        // lin1 + relu: thread (t=lane, j-group=w) computes 64 h values
        float qreg[NQv];
        #pragma unroll
        for (int n = 0; n < NQv; n++) qreg[n] = q[lane][n];
        int jg = jc * 256 + w * 64;
        #pragma unroll 4
        for (int u = 0; u < 16; u++) {
            int j = jg + 4 * u;
            float4 hv = *(const float4*)(b1v + j);
            #pragma unroll
            for (int n = 0; n < NQv; n++) {
                float4 wv = *(const float4*)(W1 + n * FFNv + j);
                hv.x += qreg[n] * wv.x; hv.y += qreg[n] * wv.y;
                hv.z += qreg[n] * wv.z; hv.w += qreg[n] * wv.w;
            }
            int jl = w * 64 + 4 * u;
            hbuf[(jl + 0) * TB + lane] = fmaxf(hv.x, 0.f);
            hbuf[(jl + 1) * TB + lane] = fmaxf(hv.y, 0.f);
            hbuf[(jl + 2) * TB + lane] = fmaxf(hv.z, 0.f);
            hbuf[(jl + 3) * TB + lane] = fmaxf(hv.w, 0.f);
        }
        __syncthreads();

        // lin2 chunk GEMM
        const float* Wp = W2 + (size_t)(jc * 256) * Ev + 4 * lane;
        #pragma unroll 2
        for (int jj = 0; jj < 256; jj++) {
            ulonglong2 A  = *(const ulonglong2*)(hbuf + jj * TB + t0);
            ulonglong2 Bt = *(const ulonglong2*)(hbuf + jj * TB + t0 + 4);
            float4 w0 = *(const float4*)(Wp + jj * Ev);
            float4 w1 = *(const float4*)(Wp + jj * Ev + 128);
            GEMM_STEP(A, Bt, w0, w1, acc);
        }
    }
    __syncthreads();   // done reading hbuf; reuse as rr

    epilogue_ln(acc, hbuf, g_x + base, b2v, g2, b2g, mbuf, vbuf,
                tid, lane, t0, g_x + base);
}

// ---------------- kernel 4a: partial pool over S slices ----------------
__global__ __launch_bounds__(256) void pool1_kernel()
{
    int b = blockIdx.x >> 3;
    int sl = blockIdx.x & 7;
    int f = threadIdx.x;
    const float* xp = g_x + (size_t)b * Sv * Ev + (size_t)sl * (Sv / 8) * Ev + f;
    float s = 0.f;
    #pragma unroll 4
    for (int i = 0; i < Sv / 8; i++) s += xp[(size_t)i * Ev];
    g_part[(b * 8 + sl) * Ev + f] = s;
}

// ---------------- kernel 4b: reduce + classifier ----------------
__global__ __launch_bounds__(256) void pool2_kernel(
    const float* __restrict__ cw, const float* __restrict__ cb,
    float* __restrict__ out)
{
    int b = blockIdx.x;
    int tid = threadIdx.x;
    float s = 0.f;
    #pragma unroll
    for (int sl = 0; sl < 8; sl++) s += g_part[(b * 8 + sl) * Ev + tid];
    float pooled = s * (1.0f / Sv);

    __shared__ float red0[256], red1[256];
    red0[tid] = pooled * cw[tid * Cv + 0];
    red1[tid] = pooled * cw[tid * Cv + 1];
    __syncthreads();
    #pragma unroll
    for (int o = 128; o > 0; o >>= 1) {
        if (tid < o) { red0[tid] += red0[tid + o]; red1[tid] += red1[tid + o]; }
        __syncthreads();
    }
    if (tid == 0) {
        out[b * Cv + 0] = red0[0] + cb[0];
        out[b * Cv + 1] = red1[0] + cb[1];
    }
}

// ---------------- launch ----------------
extern "C" void kernel_launch(void* const* d_in, const int* in_sizes, int n_in,
                              void* d_out, int out_size)
{
    const int*   tokens     = (const int*)  d_in[0];
    const float* embed      = (const float*)d_in[1];
    const float* attn_theta = (const float*)d_in[2];   // [L,64]
    const float* combine_w  = (const float*)d_in[3];   // [L,E,E]
    const float* combine_b  = (const float*)d_in[4];   // [L,E]
    const float* ffn_theta  = (const float*)d_in[5];   // [L,8]
    const float* lin1_w     = (const float*)d_in[6];   // [L,8,512]
    const float* lin1_b     = (const float*)d_in[7];   // [L,512]
    const float* lin2_w     = (const float*)d_in[8];   // [L,512,256]
    const float* lin2_b     = (const float*)d_in[9];   // [L,256]
    const float* ln1_g      = (const float*)d_in[10];
    const float* ln1_b      = (const float*)d_in[11];
    const float* ln2_g      = (const float*)d_in[12];
    const float* ln2_b      = (const float*)d_in[13];
    const float* cls_w      = (const float*)d_in[14];  // [E,2]
    const float* cls_b      = (const float*)d_in[15];  // [2]
    float* out = (float*)d_out;

    embed_pe_kernel<<<TOKENS / 8, 256>>>(tokens, embed);

    for (int l = 0; l < Lv; l++) {
        attn_ln_kernel<<<TOKENS / TB, 128>>>(
            attn_theta + l * (Ev / Hv),
            combine_w  + (size_t)l * Ev * Ev,
            combine_b  + l * Ev,
            ln1_g + l * Ev, ln1_b + l * Ev);

        ffn_ln_kernel<<<TOKENS / TB, 128>>>(
            ffn_theta + l * NQv,
            lin1_w + (size_t)l * NQv * FFNv,
            lin1_b + l * FFNv,
            lin2_w + (size_t)l * FFNv * Ev,
            lin2_b + l * Ev,
            ln2_g + l * Ev, ln2_b + l * Ev);
    }

    pool1_kernel<<<Bv * 8, 256>>>();
    pool2_kernel<<<Bv, 256>>>(cls_w, cls_b, out);
}

// round 8
// speedup vs baseline: 2.4252x; 1.0863x over previous
#include <cuda_runtime.h>
#include <cuda_bf16.h>
#include <cstdint>

// Problem constants
#define Bv   16
#define Sv   2048
#define Ev   256
#define Hv   4
#define Lv   2
#define NQv  8
#define FFNv 512
#define Cv   2
#define TOKENS (Bv * Sv)          // 32768
#define TB   32                   // tokens per block in fused layer kernels
#define WCH  16                   // weight-chunk rows staged per cp.async group

// Scratch activations [TOKENS][E] — device global (no allocation allowed)
__device__ float g_x[(size_t)TOKENS * Ev];
// pool partials [B][8][E]
__device__ float g_part[Bv * 8 * Ev];

typedef unsigned long long ull;

// ---------------- packed f32x2 helpers ----------------
__device__ __forceinline__ ull pack2(float lo, float hi) {
    ull r;
    asm("mov.b64 %0, {%1, %2};" : "=l"(r) : "f"(lo), "f"(hi));
    return r;
}
__device__ __forceinline__ void unpack2(ull v, float& lo, float& hi) {
    asm("mov.b64 {%0, %1}, %2;" : "=f"(lo), "=f"(hi) : "l"(v));
}
__device__ __forceinline__ ull ffma2(ull a, ull b, ull c) {
    ull d;
    asm("fma.rn.f32x2 %0, %1, %2, %3;" : "=l"(d) : "l"(a), "l"(b), "l"(c));
    return d;
}
__device__ __forceinline__ void cp16(uint32_t dst, const void* src) {
    asm volatile("cp.async.cg.shared.global [%0], [%1], 16;"
                 :: "r"(dst), "l"(src) : "memory");
}
__device__ __forceinline__ void cp_commit() {
    asm volatile("cp.async.commit_group;" ::: "memory");
}
__device__ __forceinline__ void cp_wait0() {
    asm volatile("cp.async.wait_group 0;" ::: "memory");
}

// ---------------- kernel 1: embedding + sinusoidal positional encoding ----------------
__global__ __launch_bounds__(256) void embed_pe_kernel(
    const int* __restrict__ tokens, const float* __restrict__ embed)
{
    int e = threadIdx.x;
    float dv = expf((float)(e & ~1) * (-9.210340371976184f / (float)Ev));
    bool odd = (e & 1);
    int tok0 = blockIdx.x * 8;
    #pragma unroll
    for (int k = 0; k < 8; k++) {
        int tok = tok0 + k;
        int s = tok & (Sv - 1);
        int id = tokens[tok];
        float arg = (float)s * dv;
        float pe = odd ? cosf(arg) : sinf(arg);
        g_x[(size_t)tok * Ev + e] = embed[(size_t)id * Ev + e] + pe;
    }
}

// ---------------- shared GEMM inner step: 8 tokens x 8 f per thread ----------------
#define GEMM_STEP(A, Bt, w0, w1, acc)                                    \
    do {                                                                 \
        ull wp;                                                          \
        wp = pack2((w0).x, (w0).x);                                      \
        acc[0][0]=ffma2((A).x,wp,acc[0][0]); acc[1][0]=ffma2((A).y,wp,acc[1][0]); \
        acc[2][0]=ffma2((Bt).x,wp,acc[2][0]); acc[3][0]=ffma2((Bt).y,wp,acc[3][0]); \
        wp = pack2((w0).y, (w0).y);                                      \
        acc[0][1]=ffma2((A).x,wp,acc[0][1]); acc[1][1]=ffma2((A).y,wp,acc[1][1]); \
        acc[2][1]=ffma2((Bt).x,wp,acc[2][1]); acc[3][1]=ffma2((Bt).y,wp,acc[3][1]); \
        wp = pack2((w0).z, (w0).z);                                      \
        acc[0][2]=ffma2((A).x,wp,acc[0][2]); acc[1][2]=ffma2((A).y,wp,acc[1][2]); \
        acc[2][2]=ffma2((Bt).x,wp,acc[2][2]); acc[3][2]=ffma2((Bt).y,wp,acc[3][2]); \
        wp = pack2((w0).w, (w0).w);                                      \
        acc[0][3]=ffma2((A).x,wp,acc[0][3]); acc[1][3]=ffma2((A).y,wp,acc[1][3]); \
        acc[2][3]=ffma2((Bt).x,wp,acc[2][3]); acc[3][3]=ffma2((Bt).y,wp,acc[3][3]); \
        wp = pack2((w1).x, (w1).x);                                      \
        acc[0][4]=ffma2((A).x,wp,acc[0][4]); acc[1][4]=ffma2((A).y,wp,acc[1][4]); \
        acc[2][4]=ffma2((Bt).x,wp,acc[2][4]); acc[3][4]=ffma2((Bt).y,wp,acc[3][4]); \
        wp = pack2((w1).y, (w1).y);                                      \
        acc[0][5]=ffma2((A).x,wp,acc[0][5]); acc[1][5]=ffma2((A).y,wp,acc[1][5]); \
        acc[2][5]=ffma2((Bt).x,wp,acc[2][5]); acc[3][5]=ffma2((Bt).y,wp,acc[3][5]); \
        wp = pack2((w1).z, (w1).z);                                      \
        acc[0][6]=ffma2((A).x,wp,acc[0][6]); acc[1][6]=ffma2((A).y,wp,acc[1][6]); \
        acc[2][6]=ffma2((Bt).x,wp,acc[2][6]); acc[3][6]=ffma2((Bt).y,wp,acc[3][6]); \
        wp = pack2((w1).w, (w1).w);                                      \
        acc[0][7]=ffma2((A).x,wp,acc[0][7]); acc[1][7]=ffma2((A).y,wp,acc[1][7]); \
        acc[2][7]=ffma2((Bt).x,wp,acc[2][7]); acc[3][7]=ffma2((Bt).y,wp,acc[3][7]); \
    } while (0)

// Epilogue+LN shared by both layer kernels. Caller must __syncthreads() first
// (rr aliases the GEMM activation buffer).
__device__ __forceinline__ void epilogue_ln(
    ull acc[4][8], float* rr, const float* xres,
    const float* __restrict__ bias, const float* __restrict__ lng,
    const float* __restrict__ lnb, float* mbuf, float* vbuf,
    int tid, int lane, int t0, float* xout)
{
    const float4 bc0 = *(const float4*)(bias + 4 * lane);
    const float4 bc1 = *(const float4*)(bias + 128 + 4 * lane);
    #pragma unroll
    for (int tp = 0; tp < 4; tp++) {
        int ta = t0 + 2 * tp;
        const float* xa = xres + (size_t)ta * Ev;
        float4 xa0 = *(const float4*)(xa + 4 * lane);
        float4 xa1 = *(const float4*)(xa + 128 + 4 * lane);
        float4 xb0 = *(const float4*)(xa + Ev + 4 * lane);
        float4 xb1 = *(const float4*)(xa + Ev + 128 + 4 * lane);
        float l0,h0,l1,h1,l2,h2,l3,h3;
        unpack2(acc[tp][0], l0, h0);
        unpack2(acc[tp][1], l1, h1);
        unpack2(acc[tp][2], l2, h2);
        unpack2(acc[tp][3], l3, h3);
        float4 ra0 = make_float4(xa0.x+l0+bc0.x, xa0.y+l1+bc0.y, xa0.z+l2+bc0.z, xa0.w+l3+bc0.w);
        float4 rb0 = make_float4(xb0.x+h0+bc0.x, xb0.y+h1+bc0.y, xb0.z+h2+bc0.z, xb0.w+h3+bc0.w);
        unpack2(acc[tp][4], l0, h0);
        unpack2(acc[tp][5], l1, h1);
        unpack2(acc[tp][6], l2, h2);
        unpack2(acc[tp][7], l3, h3);
        float4 ra1 = make_float4(xa1.x+l0+bc1.x, xa1.y+l1+bc1.y, xa1.z+l2+bc1.z, xa1.w+l3+bc1.w);
        float4 rb1 = make_float4(xb1.x+h0+bc1.x, xb1.y+h1+bc1.y, xb1.z+h2+bc1.z, xb1.w+h3+bc1.w);
        *(float4*)(rr + ta * Ev + 4 * lane)            = ra0;
        *(float4*)(rr + ta * Ev + 128 + 4 * lane)      = ra1;
        *(float4*)(rr + (ta + 1) * Ev + 4 * lane)      = rb0;
        *(float4*)(rr + (ta + 1) * Ev + 128 + 4 * lane)= rb1;
    }
    __syncthreads();

    #pragma unroll
    for (int k = 0; k < 8; k++) {
        int t = t0 + k;
        float s = 0.f, ss = 0.f;
        #pragma unroll
        for (int j = 0; j < 8; j++) {
            float v = rr[t * Ev + lane + 32 * j];
            s += v; ss += v * v;
        }
        #pragma unroll
        for (int o = 16; o > 0; o >>= 1) {
            s  += __shfl_xor_sync(0xffffffffu, s, o);
            ss += __shfl_xor_sync(0xffffffffu, ss, o);
        }
        if (lane == 0) {
            float m = s * (1.0f / Ev);
            mbuf[t] = m;
            vbuf[t] = rsqrtf(ss * (1.0f / Ev) - m * m + 1e-5f);
        }
    }
    __syncthreads();

    float gg0 = lng[tid],       bb0 = lnb[tid];
    float gg1 = lng[tid + 128], bb1 = lnb[tid + 128];
    #pragma unroll 4
    for (int t = 0; t < TB; t++) {
        float m = mbuf[t], inv = vbuf[t];
        float* xo = xout + (size_t)t * Ev;
        xo[tid]       = (rr[t * Ev + tid]       - m) * inv * gg0 + bb0;
        xo[tid + 128] = (rr[t * Ev + tid + 128] - m) * inv * gg1 + bb1;
    }
}

// ---------------- kernel 2: attn = cos(x+theta)@W + b; x = LN(x + attn) ----------------
__global__ __launch_bounds__(128, 3) void attn_ln_kernel(
    const float* __restrict__ theta,   // [64]
    const float* __restrict__ Wc,      // [E][E]
    const float* __restrict__ bc,      // [E]
    const float* __restrict__ g1, const float* __restrict__ b1)
{
    __shared__ __align__(16) float a[Ev * TB];          // [e][t] acts / later rr
    __shared__ __align__(16) float wstage[2][WCH * Ev]; // double-buffered weight chunks
    __shared__ float sth[64];
    __shared__ float mbuf[TB], vbuf[TB];

    int tid = threadIdx.x, lane = tid & 31, w = tid >> 5;
    size_t base = (size_t)blockIdx.x * TB * Ev;
    int t0 = w * 8;

    uint32_t ws0 = (uint32_t)__cvta_generic_to_shared(wstage[0]);
    uint32_t ws1 = (uint32_t)__cvta_generic_to_shared(wstage[1]);

    // stage chunk c (rows 16c..16c+15): 16KB = 128 threads x 8 x 16B
    auto stage = [&](int c) {
        const float* src = Wc + (size_t)c * WCH * Ev + tid * 4;
        uint32_t dst = ((c & 1) ? ws1 : ws0) + tid * 16;
        #pragma unroll
        for (int i = 0; i < 8; i++) cp16(dst + i * 2048, src + i * 512);
        cp_commit();
    };

    stage(0);                          // latency hides under phase A

    if (tid < 64) sth[tid] = theta[tid];
    __syncthreads();

    // Phase A: cos(x + theta), transpose to [e][t]
    {
        const float* xp = g_x + base + (size_t)lane * Ev + w * 64;
        int erow = w * 64;
        #pragma unroll
        for (int i = 0; i < 64; i += 4) {
            float4 v = *(const float4*)(xp + i);
            a[(erow + i + 0) * TB + lane] = cosf(v.x + sth[i + 0]);
            a[(erow + i + 1) * TB + lane] = cosf(v.y + sth[i + 1]);
            a[(erow + i + 2) * TB + lane] = cosf(v.z + sth[i + 2]);
            a[(erow + i + 3) * TB + lane] = cosf(v.w + sth[i + 3]);
        }
    }

    ull acc[4][8];
    #pragma unroll
    for (int p = 0; p < 4; p++)
        #pragma unroll
        for (int q = 0; q < 8; q++) acc[p][q] = 0ull;

    for (int c = 0; c < Ev / WCH; c++) {
        cp_wait0();
        // One barrier: makes chunk c visible cross-thread, publishes phase-A
        // writes (c==0), and orders last reads of chunk c-1 before stage(c+1)
        // overwrites that buffer.
        __syncthreads();
        if (c < Ev / WCH - 1) stage(c + 1);   // overlaps compute of chunk c
        const float* wb = wstage[c & 1] + 4 * lane;
        #pragma unroll 4
        for (int el = 0; el < WCH; el++) {
            int e = c * WCH + el;
            ulonglong2 A  = *(const ulonglong2*)(a + e * TB + t0);
            ulonglong2 Bt = *(const ulonglong2*)(a + e * TB + t0 + 4);
            float4 w0 = *(const float4*)(wb + el * Ev);
            float4 w1 = *(const float4*)(wb + el * Ev + 128);
            GEMM_STEP(A, Bt, w0, w1, acc);
        }
    }
    __syncthreads();   // all GEMM reads of `a` done; safe to reuse as rr

    epilogue_ln(acc, a, g_x + base, bc, g1, b1, mbuf, vbuf,
                tid, lane, t0, g_x + base);
}

// ---------------- kernel 3: FFN + LN ----------------
__global__ __launch_bounds__(128, 3) void ffn_ln_kernel(
    const float* __restrict__ fth,     // [8]
    const float* __restrict__ W1,      // [8][512]
    const float* __restrict__ b1v,     // [512]
    const float* __restrict__ W2,      // [512][256]
    const float* __restrict__ b2v,     // [256]
    const float* __restrict__ g2, const float* __restrict__ b2g)
{
    __shared__ __align__(16) float hbuf[256 * TB];      // chunk [j][t] / later rr
    __shared__ __align__(16) float wstage[2][WCH * Ev];
    __shared__ float q[TB][NQv];
    __shared__ float mbuf[TB], vbuf[TB];

    int tid = threadIdx.x, lane = tid & 31, w = tid >> 5;
    size_t base = (size_t)blockIdx.x * TB * Ev;
    int t0 = w * 8;

    uint32_t ws0 = (uint32_t)__cvta_generic_to_shared(wstage[0]);
    uint32_t ws1 = (uint32_t)__cvta_generic_to_shared(wstage[1]);

    // stage W2 chunk: 16 global rows starting at row0
    auto stage = [&](int row0, int buf) {
        const float* src = W2 + (size_t)row0 * Ev + tid * 4;
        uint32_t dst = (buf ? ws1 : ws0) + tid * 16;
        #pragma unroll
        for (int i = 0; i < 8; i++) cp16(dst + i * 2048, src + i * 512);
        cp_commit();
    };

    for (int i = tid; i < TB * NQv; i += 128) {
        int t = i >> 3, n = i & 7;
        q[t][n] = cosf(g_x[base + (size_t)t * Ev + n]) * cosf(fth[n]);
    }

    ull acc[4][8];
    #pragma unroll
    for (int p = 0; p < 4; p++)
        #pragma unroll
        for (int qq = 0; qq < 8; qq++) acc[p][qq] = 0ull;

    for (int jc = 0; jc < FFNv / 256; jc++) {
        __syncthreads();   // q ready (jc=0) / hbuf + wstage[0] fully consumed
        stage(jc * 256, 0);            // chunk-0 latency hides under lin1

        // lin1 + relu: thread (t=lane, j-group=w) computes 64 h values
        float qreg[NQv];
        #pragma unroll
        for (int n = 0; n < NQv; n++) qreg[n] = q[lane][n];
        int jg = jc * 256 + w * 64;
        #pragma unroll 4
        for (int u = 0; u < 16; u++) {
            int j = jg + 4 * u;
            float4 hv = *(const float4*)(b1v + j);
            #pragma unroll
            for (int n = 0; n < NQv; n++) {
                float4 wv = *(const float4*)(W1 + n * FFNv + j);
                hv.x += qreg[n] * wv.x; hv.y += qreg[n] * wv.y;
                hv.z += qreg[n] * wv.z; hv.w += qreg[n] * wv.w;
            }
            int jl = w * 64 + 4 * u;
            hbuf[(jl + 0) * TB + lane] = fmaxf(hv.x, 0.f);
            hbuf[(jl + 1) * TB + lane] = fmaxf(hv.y, 0.f);
            hbuf[(jl + 2) * TB + lane] = fmaxf(hv.z, 0.f);
            hbuf[(jl + 3) * TB + lane] = fmaxf(hv.w, 0.f);
        }

        for (int c = 0; c < 16; c++) {
            cp_wait0();
            // One barrier per chunk: chunk-c visibility + hbuf publication
            // (c==0) + WAR protection for stage(c+1)'s buffer.
            __syncthreads();
            if (c < 15) stage(jc * 256 + (c + 1) * WCH, (c + 1) & 1);
            const float* wb = wstage[c & 1] + 4 * lane;
            #pragma unroll 4
            for (int el = 0; el < WCH; el++) {
                int jj = c * WCH + el;
                ulonglong2 A  = *(const ulonglong2*)(hbuf + jj * TB + t0);
                ulonglong2 Bt = *(const ulonglong2*)(hbuf + jj * TB + t0 + 4);
                float4 w0 = *(const float4*)(wb + el * Ev);
                float4 w1 = *(const float4*)(wb + el * Ev + 128);
                GEMM_STEP(A, Bt, w0, w1, acc);
            }
        }
    }
    __syncthreads();   // all GEMM reads of hbuf done; safe to reuse as rr

    epilogue_ln(acc, hbuf, g_x + base, b2v, g2, b2g, mbuf, vbuf,
                tid, lane, t0, g_x + base);
}

// ---------------- kernel 4a: partial pool over S slices ----------------
__global__ __launch_bounds__(256) void pool1_kernel()
{
    int b = blockIdx.x >> 3;
    int sl = blockIdx.x & 7;
    int f = threadIdx.x;
    const float* xp = g_x + (size_t)b * Sv * Ev + (size_t)sl * (Sv / 8) * Ev + f;
    float s = 0.f;
    #pragma unroll 4
    for (int i = 0; i < Sv / 8; i++) s += xp[(size_t)i * Ev];
    g_part[(b * 8 + sl) * Ev + f] = s;
}

// ---------------- kernel 4b: reduce + classifier ----------------
__global__ __launch_bounds__(256) void pool2_kernel(
    const float* __restrict__ cw, const float* __restrict__ cb,
    float* __restrict__ out)
{
    int b = blockIdx.x;
    int tid = threadIdx.x;
    float s = 0.f;
    #pragma unroll
    for (int sl = 0; sl < 8; sl++) s += g_part[(b * 8 + sl) * Ev + tid];
    float pooled = s * (1.0f / Sv);

    __shared__ float red0[256], red1[256];
    red0[tid] = pooled * cw[tid * Cv + 0];
    red1[tid] = pooled * cw[tid * Cv + 1];
    __syncthreads();
    #pragma unroll
    for (int o = 128; o > 0; o >>= 1) {
        if (tid < o) { red0[tid] += red0[tid + o]; red1[tid] += red1[tid + o]; }
        __syncthreads();
    }
    if (tid == 0) {
        out[b * Cv + 0] = red0[0] + cb[0];
        out[b * Cv + 1] = red1[0] + cb[1];
    }
}

// ---------------- launch ----------------
extern "C" void kernel_launch(void* const* d_in, const int* in_sizes, int n_in,
                              void* d_out, int out_size)
{
    const int*   tokens     = (const int*)  d_in[0];
    const float* embed      = (const float*)d_in[1];
    const float* attn_theta = (const float*)d_in[2];   // [L,64]
    const float* combine_w  = (const float*)d_in[3];   // [L,E,E]
    const float* combine_b  = (const float*)d_in[4];   // [L,E]
    const float* ffn_theta  = (const float*)d_in[5];   // [L,8]
    const float* lin1_w     = (const float*)d_in[6];   // [L,8,512]
    const float* lin1_b     = (const float*)d_in[7];   // [L,512]
    const float* lin2_w     = (const float*)d_in[8];   // [L,512,256]
    const float* lin2_b     = (const float*)d_in[9];   // [L,256]
    const float* ln1_g      = (const float*)d_in[10];
    const float* ln1_b      = (const float*)d_in[11];
    const float* ln2_g      = (const float*)d_in[12];
    const float* ln2_b      = (const float*)d_in[13];
    const float* cls_w      = (const float*)d_in[14];  // [E,2]
    const float* cls_b      = (const float*)d_in[15];  // [2]
    float* out = (float*)d_out;

    embed_pe_kernel<<<TOKENS / 8, 256>>>(tokens, embed);

    for (int l = 0; l < Lv; l++) {
        attn_ln_kernel<<<TOKENS / TB, 128>>>(
            attn_theta + l * (Ev / Hv),
            combine_w  + (size_t)l * Ev * Ev,
            combine_b  + l * Ev,
            ln1_g + l * Ev, ln1_b + l * Ev);

        ffn_ln_kernel<<<TOKENS / TB, 128>>>(
            ffn_theta + l * NQv,
            lin1_w + (size_t)l * NQv * FFNv,
            lin1_b + l * FFNv,
            lin2_w + (size_t)l * FFNv * Ev,
            lin2_b + l * Ev,
            ln2_g + l * Ev, ln2_b + l * Ev);
    }

    pool1_kernel<<<Bv * 8, 256>>>();
    pool2_kernel<<<Bv, 256>>>(cls_w, cls_b, out);
}